// round 4
// baseline (speedup 1.0000x reference)
#include <cuda_runtime.h>

#define B_   128
#define T_   196
#define TT_  392      // 2*T
#define ENC_ 1024
#define DEC_ 512
#define V_   98
#define M_   294

// position of the v-th visible token for each batch row (scratch)
__device__ int g_vis_pos[B_ * V_];

// ---------------------------------------------------------------------------
// Kernel 1: per batch row, compute visible positions (ascending complement of
// masked_ids) via a block-wide inclusive scan over 392 flags.
// masked_ids is int32 (JAX x64 disabled: jnp.int64 -> int32 on device).
// ---------------------------------------------------------------------------
__global__ void build_map_kernel(const int* __restrict__ masked_ids) {
    __shared__ int flags[TT_];
    __shared__ int scan[TT_];
    const int b   = blockIdx.x;
    const int tid = threadIdx.x;   // 512 threads

    if (tid < TT_) flags[tid] = 1;
    __syncthreads();
    if (tid < M_) flags[masked_ids[b * M_ + tid]] = 0;
    __syncthreads();
    if (tid < TT_) scan[tid] = flags[tid];
    __syncthreads();
    for (int off = 1; off < TT_; off <<= 1) {
        int v = 0;
        if (tid < TT_ && tid >= off) v = scan[tid - off];
        __syncthreads();
        if (tid < TT_) scan[tid] += v;
        __syncthreads();
    }
    if (tid < TT_ && flags[tid]) g_vis_pos[b * V_ + scan[tid] - 1] = tid;
}

// ---------------------------------------------------------------------------
// Kernel 2: fill the 294 masked positions per row with
// mask_token + pos_embed + view_embed. Disjoint from the GEMM's scatter, so
// every output element is written exactly once.
// ---------------------------------------------------------------------------
__global__ void fill_masked_kernel(const int* __restrict__ masked_ids,
                                   const float* __restrict__ mask_token,
                                   const float* __restrict__ pos_embed,
                                   const float* __restrict__ view_embed,
                                   float* __restrict__ out) {
    const int m = blockIdx.x;
    const int b = blockIdx.y;
    const int pos = masked_ids[b * M_ + m];
    const int d = threadIdx.x * 4;   // 128 threads * 4 floats = 512

    float4 mt = *(const float4*)(mask_token + d);
    float4 pe = *(const float4*)(pos_embed + (size_t)pos * DEC_ + d);
    float4 ve = *(const float4*)(view_embed + (pos >= T_ ? DEC_ : 0) + d);
    float4 r;
    r.x = mt.x + pe.x + ve.x;
    r.y = mt.y + pe.y + ve.y;
    r.z = mt.z + pe.z + ve.z;
    r.w = mt.w + pe.w + ve.w;
    *(float4*)(out + ((size_t)b * TT_ + pos) * DEC_ + d) = r;
}

// ---------------------------------------------------------------------------
// Kernel 3: tiled fp32 GEMM C[r,n] = sum_k x[r,k] * W[n,k]  (r = b*V + v)
// 128x128 CTA tile, K-tile 8, 256 threads, 8x8 register blocking,
// double-buffered smem. Epilogue scatters row r to out[b, vis_pos[r], :]
// adding bias + pos_embed + view_embed.
// ---------------------------------------------------------------------------
__global__ __launch_bounds__(256)
void gemm_scatter_kernel(const float* __restrict__ x,     // (B*V, ENC)
                         const float* __restrict__ Wm,    // (DEC, ENC)
                         const float* __restrict__ bias,  // (DEC)
                         const float* __restrict__ pos_embed,  // (2T, DEC)
                         const float* __restrict__ view_embed, // (2, DEC)
                         float* __restrict__ out) {
    __shared__ float As[2][8][128];
    __shared__ float Bs[2][8][128];

    const int tid = threadIdx.x;
    const int m0 = blockIdx.x * 128;   // 98 tiles, 12544 rows exactly
    const int n0 = blockIdx.y * 128;   // 4 tiles

    // global->smem load mapping: 256 threads * float4 = 128 rows * 8 k
    const int lr = tid >> 1;           // row within tile 0..127
    const int lk = (tid & 1) * 4;      // k offset 0 or 4
    const float* ap = x  + (size_t)(m0 + lr) * ENC_ + lk;
    const float* bp = Wm + (size_t)(n0 + lr) * ENC_ + lk;

    // prologue: tile 0
    {
        float4 a4 = *(const float4*)ap;
        float4 b4 = *(const float4*)bp;
        As[0][lk + 0][lr] = a4.x;
        As[0][lk + 1][lr] = a4.y;
        As[0][lk + 2][lr] = a4.z;
        As[0][lk + 3][lr] = a4.w;
        Bs[0][lk + 0][lr] = b4.x;
        Bs[0][lk + 1][lr] = b4.y;
        Bs[0][lk + 2][lr] = b4.z;
        Bs[0][lk + 3][lr] = b4.w;
    }
    __syncthreads();

    const int ty = tid >> 4;   // 0..15 -> 8 rows each
    const int tx = tid & 15;   // 0..15 -> 8 cols each

    float acc[8][8];
#pragma unroll
    for (int i = 0; i < 8; i++)
#pragma unroll
        for (int j = 0; j < 8; j++) acc[i][j] = 0.0f;

    int buf = 0;
    for (int kt = 8; kt <= ENC_; kt += 8) {
        const bool has_next = (kt < ENC_);
        float4 a4n, b4n;
        if (has_next) {
            a4n = *(const float4*)(ap + kt);
            b4n = *(const float4*)(bp + kt);
        }
#pragma unroll
        for (int kk = 0; kk < 8; kk++) {
            float af[8], bf[8];
            *(float4*)(af)     = *(const float4*)&As[buf][kk][ty * 8];
            *(float4*)(af + 4) = *(const float4*)&As[buf][kk][ty * 8 + 4];
            *(float4*)(bf)     = *(const float4*)&Bs[buf][kk][tx * 8];
            *(float4*)(bf + 4) = *(const float4*)&Bs[buf][kk][tx * 8 + 4];
#pragma unroll
            for (int i = 0; i < 8; i++)
#pragma unroll
                for (int j = 0; j < 8; j++)
                    acc[i][j] += af[i] * bf[j];
        }
        if (has_next) {
            const int nb = buf ^ 1;
            As[nb][lk + 0][lr] = a4n.x;
            As[nb][lk + 1][lr] = a4n.y;
            As[nb][lk + 2][lr] = a4n.z;
            As[nb][lk + 3][lr] = a4n.w;
            Bs[nb][lk + 0][lr] = b4n.x;
            Bs[nb][lk + 1][lr] = b4n.y;
            Bs[nb][lk + 2][lr] = b4n.z;
            Bs[nb][lk + 3][lr] = b4n.w;
            __syncthreads();
            buf = nb;
        }
    }

    // epilogue: scatter with bias + pos_embed + view_embed
    float bias_f[8];
    *(float4*)(bias_f)     = *(const float4*)(bias + n0 + tx * 8);
    *(float4*)(bias_f + 4) = *(const float4*)(bias + n0 + tx * 8 + 4);

#pragma unroll
    for (int i = 0; i < 8; i++) {
        const int r   = m0 + ty * 8 + i;
        const int bb  = r / V_;
        const int pos = g_vis_pos[r];
        const float* pe = pos_embed  + (size_t)pos * DEC_ + n0 + tx * 8;
        const float* ve = view_embed + (pos >= T_ ? DEC_ : 0) + n0 + tx * 8;
        float* op = out + ((size_t)bb * TT_ + pos) * DEC_ + n0 + tx * 8;

        float4 pe0 = *(const float4*)pe;
        float4 pe1 = *(const float4*)(pe + 4);
        float4 ve0 = *(const float4*)ve;
        float4 ve1 = *(const float4*)(ve + 4);
        float4 o0, o1;
        o0.x = acc[i][0] + bias_f[0] + pe0.x + ve0.x;
        o0.y = acc[i][1] + bias_f[1] + pe0.y + ve0.y;
        o0.z = acc[i][2] + bias_f[2] + pe0.z + ve0.z;
        o0.w = acc[i][3] + bias_f[3] + pe0.w + ve0.w;
        o1.x = acc[i][4] + bias_f[4] + pe1.x + ve1.x;
        o1.y = acc[i][5] + bias_f[5] + pe1.y + ve1.y;
        o1.z = acc[i][6] + bias_f[6] + pe1.z + ve1.z;
        o1.w = acc[i][7] + bias_f[7] + pe1.w + ve1.w;
        *(float4*)op       = o0;
        *(float4*)(op + 4) = o1;
    }
}

// ---------------------------------------------------------------------------
extern "C" void kernel_launch(void* const* d_in, const int* in_sizes, int n_in,
                              void* d_out, int out_size) {
    const float* x          = (const float*)d_in[0];
    const int*   masked_ids = (const int*)d_in[1];
    const float* Wm         = (const float*)d_in[2];
    const float* bias       = (const float*)d_in[3];
    const float* mask_token = (const float*)d_in[4];
    const float* pos_embed  = (const float*)d_in[5];
    const float* view_embed = (const float*)d_in[6];
    float*       out        = (float*)d_out;

    build_map_kernel<<<B_, 512>>>(masked_ids);
    fill_masked_kernel<<<dim3(M_, B_), 128>>>(masked_ids, mask_token,
                                              pos_embed, view_embed, out);
    gemm_scatter_kernel<<<dim3(98, 4), 256>>>(x, Wm, bias, pos_embed,
                                              view_embed, out);
}

// round 6
// speedup vs baseline: 2.4873x; 2.4873x over previous
#include <cuda_runtime.h>
#include <cuda_bf16.h>
#include <cstdint>

#define B_   128
#define T_   196
#define TT_  392      // 2*T
#define ENC_ 1024
#define DEC_ 512
#define V_   98
#define M_   294

// GEMM tiling
#define BM_   128
#define BN_   128
#define BK_   32           // fp32 K elements per chunk
#define NCH_  32           // 1024 / 32
#define PADB_ 80           // bytes per smem row (32 bf16 = 64B, padded to 80)
#define A_HI  0
#define A_LO  10240
#define B_HI  20480
#define B_LO  30720
#define STG_  40960
#define SMEM_TOTAL (2 * STG_)   // 81920

// position of the v-th visible token for each batch row (scratch)
__device__ int g_vis_pos[B_ * V_];

// ---------------------------------------------------------------------------
// helpers
// ---------------------------------------------------------------------------
__device__ __forceinline__ uint32_t smem_u32(const void* p) {
    uint32_t a;
    asm("{ .reg .u64 t; cvta.to.shared.u64 t, %1; cvt.u32.u64 %0, t; }"
        : "=r"(a) : "l"(p));
    return a;
}
__device__ __forceinline__ void ldsm_x4(uint32_t* r, uint32_t addr) {
    asm volatile("ldmatrix.sync.aligned.m8n8.x4.shared.b16 {%0,%1,%2,%3}, [%4];"
                 : "=r"(r[0]), "=r"(r[1]), "=r"(r[2]), "=r"(r[3]) : "r"(addr));
}
__device__ __forceinline__ void ldsm_x2(uint32_t* r, uint32_t addr) {
    asm volatile("ldmatrix.sync.aligned.m8n8.x2.shared.b16 {%0,%1}, [%2];"
                 : "=r"(r[0]), "=r"(r[1]) : "r"(addr));
}
__device__ __forceinline__ void mma16816(float* d, const uint32_t* a, const uint32_t* b) {
    asm volatile("mma.sync.aligned.m16n8k16.row.col.f32.bf16.bf16.f32 "
                 "{%0,%1,%2,%3},{%4,%5,%6,%7},{%8,%9},{%0,%1,%2,%3};"
                 : "+f"(d[0]), "+f"(d[1]), "+f"(d[2]), "+f"(d[3])
                 : "r"(a[0]), "r"(a[1]), "r"(a[2]), "r"(a[3]),
                   "r"(b[0]), "r"(b[1]));
}
__device__ __forceinline__ uint32_t pack_bf2(__nv_bfloat16 a, __nv_bfloat16 b) {
    return (uint32_t)__bfloat16_as_ushort(a) | ((uint32_t)__bfloat16_as_ushort(b) << 16);
}
// split float4 into hi bf16x4 (8B) and lo bf16x4 (8B)
__device__ __forceinline__ void split_f4(float4 f, uint2& hi, uint2& lo) {
    __nv_bfloat16 h0 = __float2bfloat16(f.x);
    __nv_bfloat16 h1 = __float2bfloat16(f.y);
    __nv_bfloat16 h2 = __float2bfloat16(f.z);
    __nv_bfloat16 h3 = __float2bfloat16(f.w);
    __nv_bfloat16 l0 = __float2bfloat16(f.x - __bfloat162float(h0));
    __nv_bfloat16 l1 = __float2bfloat16(f.y - __bfloat162float(h1));
    __nv_bfloat16 l2 = __float2bfloat16(f.z - __bfloat162float(h2));
    __nv_bfloat16 l3 = __float2bfloat16(f.w - __bfloat162float(h3));
    hi.x = pack_bf2(h0, h1); hi.y = pack_bf2(h2, h3);
    lo.x = pack_bf2(l0, l1); lo.y = pack_bf2(l2, l3);
}

// ---------------------------------------------------------------------------
// Kernel 1: visible positions via block scan (unchanged, passed R4)
// ---------------------------------------------------------------------------
__global__ void build_map_kernel(const int* __restrict__ masked_ids) {
    __shared__ int flags[TT_];
    __shared__ int scan[TT_];
    const int b   = blockIdx.x;
    const int tid = threadIdx.x;   // 512

    if (tid < TT_) flags[tid] = 1;
    __syncthreads();
    if (tid < M_) flags[masked_ids[b * M_ + tid]] = 0;
    __syncthreads();
    if (tid < TT_) scan[tid] = flags[tid];
    __syncthreads();
    for (int off = 1; off < TT_; off <<= 1) {
        int v = 0;
        if (tid < TT_ && tid >= off) v = scan[tid - off];
        __syncthreads();
        if (tid < TT_) scan[tid] += v;
        __syncthreads();
    }
    if (tid < TT_ && flags[tid]) g_vis_pos[b * V_ + scan[tid] - 1] = tid;
}

// ---------------------------------------------------------------------------
// Kernel 2: fill 294 masked positions (unchanged, passed R4)
// ---------------------------------------------------------------------------
__global__ void fill_masked_kernel(const int* __restrict__ masked_ids,
                                   const float* __restrict__ mask_token,
                                   const float* __restrict__ pos_embed,
                                   const float* __restrict__ view_embed,
                                   float* __restrict__ out) {
    const int m = blockIdx.x;
    const int b = blockIdx.y;
    const int pos = masked_ids[b * M_ + m];
    const int d = threadIdx.x * 4;

    float4 mt = *(const float4*)(mask_token + d);
    float4 pe = *(const float4*)(pos_embed + (size_t)pos * DEC_ + d);
    float4 ve = *(const float4*)(view_embed + (pos >= T_ ? DEC_ : 0) + d);
    float4 r;
    r.x = mt.x + pe.x + ve.x;
    r.y = mt.y + pe.y + ve.y;
    r.z = mt.z + pe.z + ve.z;
    r.w = mt.w + pe.w + ve.w;
    *(float4*)(out + ((size_t)b * TT_ + pos) * DEC_ + d) = r;
}

// ---------------------------------------------------------------------------
// Kernel 3: mma.sync bf16 (3-product hi/lo split) GEMM + fused scatter.
// C[r,n] = sum_k x[r,k] * W[n,k].  128x128 tile, K-chunk 32, 8 warps.
// ---------------------------------------------------------------------------
__global__ __launch_bounds__(256)
void gemm_mma_kernel(const float* __restrict__ x,     // (12544, 1024)
                     const float* __restrict__ Wm,    // (512, 1024)
                     const float* __restrict__ bias,
                     const float* __restrict__ pos_embed,
                     const float* __restrict__ view_embed,
                     float* __restrict__ out) {
    extern __shared__ char smem[];
    const uint32_t sb  = smem_u32(smem);
    const int tid = threadIdx.x;
    const int lid = tid & 31;
    const int wid = tid >> 5;
    const int wm  = wid & 3;          // 4 m-warps of 32 rows
    const int wn  = wid >> 2;         // 2 n-warps of 64 cols
    const int m0  = blockIdx.x * BM_;
    const int n0  = blockIdx.y * BN_;

    // gmem load mapping: idx = tid + j*256; row = idx>>3, seg = idx&7
    const int grow = tid >> 3;        // base row, +32 per j
    const int gseg = tid & 7;
    const float* ap = x  + (size_t)(m0 + grow) * ENC_ + gseg * 4;
    const float* bp = Wm + (size_t)(n0 + grow) * ENC_ + gseg * 4;
    const uint32_t sts_off = (uint32_t)(grow * PADB_ + gseg * 8);

    // ldmatrix lane coords
    const int a_r  = (lid & 7) + ((lid >> 3) & 1) * 8;   // row within m16 tile
    const int a_kh = lid >> 4;                            // k half (0/1)
    const int b_r  = lid & 7;                             // row within n8 tile
    const int b_kh = (lid >> 3) & 1;

    float acc[2][8][4];
#pragma unroll
    for (int i = 0; i < 2; i++)
#pragma unroll
        for (int j = 0; j < 8; j++)
#pragma unroll
            for (int c = 0; c < 4; c++) acc[i][j][c] = 0.0f;

    float4 ra[4], rb[4];

    // ---- prologue: chunk 0 ----
#pragma unroll
    for (int j = 0; j < 4; j++) {
        ra[j] = *(const float4*)(ap + (size_t)j * 32 * ENC_);
        rb[j] = *(const float4*)(bp + (size_t)j * 32 * ENC_);
    }
#pragma unroll
    for (int j = 0; j < 4; j++) {
        uint2 hi, lo;
        split_f4(ra[j], hi, lo);
        *(uint2*)(smem + A_HI + sts_off + j * 32 * PADB_) = hi;
        *(uint2*)(smem + A_LO + sts_off + j * 32 * PADB_) = lo;
        split_f4(rb[j], hi, lo);
        *(uint2*)(smem + B_HI + sts_off + j * 32 * PADB_) = hi;
        *(uint2*)(smem + B_LO + sts_off + j * 32 * PADB_) = lo;
    }
    __syncthreads();

    for (int ch = 0; ch < NCH_; ch++) {
        const uint32_t stg = (uint32_t)(ch & 1) * STG_;
        const bool has_next = (ch + 1 < NCH_);

        // prefetch next chunk to registers
        if (has_next) {
            const int k0 = (ch + 1) * BK_;
#pragma unroll
            for (int j = 0; j < 4; j++) {
                ra[j] = *(const float4*)(ap + (size_t)j * 32 * ENC_ + k0);
                rb[j] = *(const float4*)(bp + (size_t)j * 32 * ENC_ + k0);
            }
        }

        // compute on current buffer
#pragma unroll
        for (int ks = 0; ks < 2; ks++) {
            uint32_t aH[2][4], aL[2][4];
#pragma unroll
            for (int i = 0; i < 2; i++) {
                uint32_t ad = sb + stg + A_HI
                            + (uint32_t)((wm * 32 + i * 16 + a_r) * PADB_
                                         + (ks * 16 + a_kh * 8) * 2);
                ldsm_x4(aH[i], ad);
                ldsm_x4(aL[i], ad + (A_LO - A_HI));
            }
#pragma unroll
            for (int j = 0; j < 8; j++) {
                uint32_t bd = sb + stg + B_HI
                            + (uint32_t)((wn * 64 + j * 8 + b_r) * PADB_
                                         + (ks * 16 + b_kh * 8) * 2);
                uint32_t bh[2], bl[2];
                ldsm_x2(bh, bd);
                ldsm_x2(bl, bd + (B_LO - B_HI));
#pragma unroll
                for (int i = 0; i < 2; i++) {
                    mma16816(acc[i][j], aH[i], bh);
                    mma16816(acc[i][j], aH[i], bl);
                    mma16816(acc[i][j], aL[i], bh);
                }
            }
        }

        if (has_next) {
            const uint32_t nstg = (uint32_t)((ch + 1) & 1) * STG_;
#pragma unroll
            for (int j = 0; j < 4; j++) {
                uint2 hi, lo;
                split_f4(ra[j], hi, lo);
                *(uint2*)(smem + nstg + A_HI + sts_off + j * 32 * PADB_) = hi;
                *(uint2*)(smem + nstg + A_LO + sts_off + j * 32 * PADB_) = lo;
                split_f4(rb[j], hi, lo);
                *(uint2*)(smem + nstg + B_HI + sts_off + j * 32 * PADB_) = hi;
                *(uint2*)(smem + nstg + B_LO + sts_off + j * 32 * PADB_) = lo;
            }
            __syncthreads();
        }
    }

    // ---- epilogue: scatter with bias + pos_embed + view_embed ----
    const int qrow = lid >> 2;        // 0..7
    const int qcol = (lid & 3) * 2;   // 0,2,4,6
#pragma unroll
    for (int i = 0; i < 2; i++) {
#pragma unroll
        for (int half = 0; half < 2; half++) {
            const int m   = wm * 32 + i * 16 + qrow + half * 8;
            const int r   = m0 + m;
            const int bb  = r / V_;
            const int pos = g_vis_pos[r];
            const float* pe = pos_embed  + (size_t)pos * DEC_;
            const float* ve = view_embed + (pos >= T_ ? DEC_ : 0);
            float* op = out + ((size_t)bb * TT_ + pos) * DEC_;
#pragma unroll
            for (int j = 0; j < 8; j++) {
                const int n = n0 + wn * 64 + j * 8 + qcol;
                float2 o;
                o.x = acc[i][j][half * 2 + 0] + bias[n]     + pe[n]     + ve[n];
                o.y = acc[i][j][half * 2 + 1] + bias[n + 1] + pe[n + 1] + ve[n + 1];
                *(float2*)(op + n) = o;
            }
        }
    }
}

// ---------------------------------------------------------------------------
extern "C" void kernel_launch(void* const* d_in, const int* in_sizes, int n_in,
                              void* d_out, int out_size) {
    const float* x          = (const float*)d_in[0];
    const int*   masked_ids = (const int*)d_in[1];
    const float* Wm         = (const float*)d_in[2];
    const float* bias       = (const float*)d_in[3];
    const float* mask_token = (const float*)d_in[4];
    const float* pos_embed  = (const float*)d_in[5];
    const float* view_embed = (const float*)d_in[6];
    float*       out        = (float*)d_out;

    cudaFuncSetAttribute(gemm_mma_kernel,
                         cudaFuncAttributeMaxDynamicSharedMemorySize, SMEM_TOTAL);

    build_map_kernel<<<B_, 512>>>(masked_ids);
    fill_masked_kernel<<<dim3(M_, B_), 128>>>(masked_ids, mask_token,
                                              pos_embed, view_embed, out);
    gemm_mma_kernel<<<dim3(98, 4), 256, SMEM_TOTAL>>>(x, Wm, bias, pos_embed,
                                                      view_embed, out);
}

// round 7
// speedup vs baseline: 2.8401x; 1.1418x over previous
#include <cuda_runtime.h>
#include <cuda_bf16.h>
#include <cstdint>

#define B_   128
#define T_   196
#define TT_  392      // 2*T
#define ENC_ 1024
#define DEC_ 512
#define V_   98
#define M_   294

// GEMM tiling
#define BM_   128
#define BN_   128
#define BK_   32           // fp32 K elements per chunk
#define NCH_  32           // 1024 / 32
#define PADB_ 80           // bytes per smem row (32 bf16 = 64B, padded to 80)
#define A_HI  0
#define A_LO  10240
#define B_HI  20480
#define B_LO  30720
#define STG_  40960
#define SMEM_TOTAL (2 * STG_)   // 81920

#define NGEMM_ 392          // 98 * 4 gemm CTAs
#define NFILL_ 96           // fill CTAs fused into the tail
#define NWORK_ (M_ * B_)    // 37632 masked row-fills

// position of the v-th visible token for each batch row (scratch)
__device__ int g_vis_pos[B_ * V_];

// ---------------------------------------------------------------------------
// helpers
// ---------------------------------------------------------------------------
__device__ __forceinline__ uint32_t smem_u32(const void* p) {
    uint32_t a;
    asm("{ .reg .u64 t; cvta.to.shared.u64 t, %1; cvt.u32.u64 %0, t; }"
        : "=r"(a) : "l"(p));
    return a;
}
__device__ __forceinline__ void ldsm_x4(uint32_t* r, uint32_t addr) {
    asm volatile("ldmatrix.sync.aligned.m8n8.x4.shared.b16 {%0,%1,%2,%3}, [%4];"
                 : "=r"(r[0]), "=r"(r[1]), "=r"(r[2]), "=r"(r[3]) : "r"(addr));
}
__device__ __forceinline__ void ldsm_x2(uint32_t* r, uint32_t addr) {
    asm volatile("ldmatrix.sync.aligned.m8n8.x2.shared.b16 {%0,%1}, [%2];"
                 : "=r"(r[0]), "=r"(r[1]) : "r"(addr));
}
__device__ __forceinline__ void mma16816(float* d, const uint32_t* a, const uint32_t* b) {
    asm volatile("mma.sync.aligned.m16n8k16.row.col.f32.bf16.bf16.f32 "
                 "{%0,%1,%2,%3},{%4,%5,%6,%7},{%8,%9},{%0,%1,%2,%3};"
                 : "+f"(d[0]), "+f"(d[1]), "+f"(d[2]), "+f"(d[3])
                 : "r"(a[0]), "r"(a[1]), "r"(a[2]), "r"(a[3]),
                   "r"(b[0]), "r"(b[1]));
}
__device__ __forceinline__ uint32_t pack_bf2(__nv_bfloat16 a, __nv_bfloat16 b) {
    return (uint32_t)__bfloat16_as_ushort(a) | ((uint32_t)__bfloat16_as_ushort(b) << 16);
}
// split float4 into hi bf16x4 (8B) and lo bf16x4 (8B)
__device__ __forceinline__ void split_f4(float4 f, uint2& hi, uint2& lo) {
    __nv_bfloat16 h0 = __float2bfloat16(f.x);
    __nv_bfloat16 h1 = __float2bfloat16(f.y);
    __nv_bfloat16 h2 = __float2bfloat16(f.z);
    __nv_bfloat16 h3 = __float2bfloat16(f.w);
    __nv_bfloat16 l0 = __float2bfloat16(f.x - __bfloat162float(h0));
    __nv_bfloat16 l1 = __float2bfloat16(f.y - __bfloat162float(h1));
    __nv_bfloat16 l2 = __float2bfloat16(f.z - __bfloat162float(h2));
    __nv_bfloat16 l3 = __float2bfloat16(f.w - __bfloat162float(h3));
    hi.x = pack_bf2(h0, h1); hi.y = pack_bf2(h2, h3);
    lo.x = pack_bf2(l0, l1); lo.y = pack_bf2(l2, l3);
}

// ---------------------------------------------------------------------------
// Kernel 1: visible positions via block scan
// ---------------------------------------------------------------------------
__global__ void build_map_kernel(const int* __restrict__ masked_ids) {
    __shared__ int flags[TT_];
    __shared__ int scan[TT_];
    const int b   = blockIdx.x;
    const int tid = threadIdx.x;   // 512

    if (tid < TT_) flags[tid] = 1;
    __syncthreads();
    if (tid < M_) flags[masked_ids[b * M_ + tid]] = 0;
    __syncthreads();
    if (tid < TT_) scan[tid] = flags[tid];
    __syncthreads();
    for (int off = 1; off < TT_; off <<= 1) {
        int v = 0;
        if (tid < TT_ && tid >= off) v = scan[tid - off];
        __syncthreads();
        if (tid < TT_) scan[tid] += v;
        __syncthreads();
    }
    if (tid < TT_ && flags[tid]) g_vis_pos[b * V_ + scan[tid] - 1] = tid;
}

// ---------------------------------------------------------------------------
// Fused kernel: bids [0,392) = mma.sync GEMM tiles + scatter epilogue,
//               bids [392,488) = masked-position fill (runs in the GEMM tail).
// ---------------------------------------------------------------------------
__global__ __launch_bounds__(256, 2)
void gemm_fused_kernel(const float* __restrict__ x,     // (12544, 1024)
                       const float* __restrict__ Wm,    // (512, 1024)
                       const float* __restrict__ bias,
                       const float* __restrict__ pos_embed,
                       const float* __restrict__ view_embed,
                       const int*   __restrict__ masked_ids,
                       const float* __restrict__ mask_token,
                       float* __restrict__ out) {
    const int bid = blockIdx.x;
    const int tid = threadIdx.x;

    // ======================= FILL branch =======================
    if (bid >= NGEMM_) {
        const int f = bid - NGEMM_;
        const int d0 = (tid & 127) * 4;          // 128 segs of float4
        const int half = tid >> 7;               // 2 row-fills per iteration
        float4 mt0 = *(const float4*)(mask_token + d0);
        for (int w = f * 2 + half; w < NWORK_; w += NFILL_ * 2) {
            const int b = w / M_;
            const int m = w - b * M_;
            const int pos = masked_ids[b * M_ + m];
            float4 pe = *(const float4*)(pos_embed + (size_t)pos * DEC_ + d0);
            float4 ve = *(const float4*)(view_embed + (pos >= T_ ? DEC_ : 0) + d0);
            float4 r;
            r.x = mt0.x + pe.x + ve.x;
            r.y = mt0.y + pe.y + ve.y;
            r.z = mt0.z + pe.z + ve.z;
            r.w = mt0.w + pe.w + ve.w;
            *(float4*)(out + ((size_t)b * TT_ + pos) * DEC_ + d0) = r;
        }
        return;
    }

    // ======================= GEMM branch =======================
    extern __shared__ char smem[];
    const uint32_t sb  = smem_u32(smem);
    const int lid = tid & 31;
    const int wid = tid >> 5;
    const int wm  = wid & 3;          // 4 m-warps of 32 rows
    const int wn  = wid >> 2;         // 2 n-warps of 64 cols
    const int m0  = (bid % 98) * BM_;
    const int n0  = (bid / 98) * BN_;

    // gmem load mapping: idx = tid + j*256; row = idx>>3, seg = idx&7
    const int grow = tid >> 3;        // base row, +32 per j
    const int gseg = tid & 7;
    const float* ap = x  + (size_t)(m0 + grow) * ENC_ + gseg * 4;
    const float* bp = Wm + (size_t)(n0 + grow) * ENC_ + gseg * 4;
    const uint32_t sts_off = (uint32_t)(grow * PADB_ + gseg * 8);

    // ldmatrix lane coords
    const int a_r  = (lid & 7) + ((lid >> 3) & 1) * 8;
    const int a_kh = lid >> 4;
    const int b_r  = lid & 7;
    const int b_kh = (lid >> 3) & 1;
    const uint32_t a_base = sb + A_HI
        + (uint32_t)((wm * 32 + a_r) * PADB_ + a_kh * 16);
    const uint32_t b_base = sb + B_HI
        + (uint32_t)((wn * 64 + b_r) * PADB_ + b_kh * 16);

    float acc[2][8][4];
#pragma unroll
    for (int i = 0; i < 2; i++)
#pragma unroll
        for (int j = 0; j < 8; j++)
#pragma unroll
            for (int c = 0; c < 4; c++) acc[i][j][c] = 0.0f;

    // ---- prologue: chunk 0 into stage 0 ----
#pragma unroll
    for (int j = 0; j < 4; j++) {
        float4 fa = *(const float4*)(ap + (size_t)j * 32 * ENC_);
        float4 fb = *(const float4*)(bp + (size_t)j * 32 * ENC_);
        uint2 hi, lo;
        split_f4(fa, hi, lo);
        *(uint2*)(smem + A_HI + sts_off + j * 32 * PADB_) = hi;
        *(uint2*)(smem + A_LO + sts_off + j * 32 * PADB_) = lo;
        split_f4(fb, hi, lo);
        *(uint2*)(smem + B_HI + sts_off + j * 32 * PADB_) = hi;
        *(uint2*)(smem + B_LO + sts_off + j * 32 * PADB_) = lo;
    }
    __syncthreads();

    for (int ch = 0; ch < NCH_; ch++) {
        const uint32_t stg = (uint32_t)(ch & 1) * STG_;
        const bool has_next = (ch + 1 < NCH_);

        // ---- compute ks = 0 ----
#pragma unroll
        for (int ks = 0; ks < 2; ks++) {
            uint32_t aH[2][4], aL[2][4];
#pragma unroll
            for (int i = 0; i < 2; i++) {
                uint32_t ad = a_base + stg + (uint32_t)(i * 16 * PADB_ + ks * 32);
                ldsm_x4(aH[i], ad);
                ldsm_x4(aL[i], ad + (A_LO - A_HI));
            }
#pragma unroll
            for (int j = 0; j < 8; j++) {
                uint32_t bd = b_base + stg + (uint32_t)(j * 8 * PADB_ + ks * 32);
                uint32_t bh[2], bl[2];
                ldsm_x2(bh, bd);
                ldsm_x2(bl, bd + (B_LO - B_HI));
#pragma unroll
                for (int i = 0; i < 2; i++) {
                    mma16816(acc[i][j], aH[i], bh);
                    mma16816(acc[i][j], aH[i], bl);
                    mma16816(acc[i][j], aL[i], bh);
                }
            }
            // between the two K-halves: stream next chunk to the other stage
            if (ks == 0 && has_next) {
                const int k0 = (ch + 1) * BK_;
                const uint32_t nstg = (uint32_t)((ch + 1) & 1) * STG_;
#pragma unroll
                for (int j = 0; j < 4; j++) {
                    float4 fa = *(const float4*)(ap + (size_t)j * 32 * ENC_ + k0);
                    float4 fb = *(const float4*)(bp + (size_t)j * 32 * ENC_ + k0);
                    uint2 hi, lo;
                    split_f4(fa, hi, lo);
                    *(uint2*)(smem + nstg + A_HI + sts_off + j * 32 * PADB_) = hi;
                    *(uint2*)(smem + nstg + A_LO + sts_off + j * 32 * PADB_) = lo;
                    split_f4(fb, hi, lo);
                    *(uint2*)(smem + nstg + B_HI + sts_off + j * 32 * PADB_) = hi;
                    *(uint2*)(smem + nstg + B_LO + sts_off + j * 32 * PADB_) = lo;
                }
            }
        }
        __syncthreads();
    }

    // ---- epilogue: scatter with bias + pos_embed + view_embed ----
    const int qrow = lid >> 2;        // 0..7
    const int qcol = (lid & 3) * 2;   // 0,2,4,6
#pragma unroll
    for (int i = 0; i < 2; i++) {
#pragma unroll
        for (int half = 0; half < 2; half++) {
            const int m   = wm * 32 + i * 16 + qrow + half * 8;
            const int r   = m0 + m;
            const int bb  = r / V_;
            const int pos = g_vis_pos[r];
            const float* pe = pos_embed  + (size_t)pos * DEC_;
            const float* ve = view_embed + (pos >= T_ ? DEC_ : 0);
            float* op = out + ((size_t)bb * TT_ + pos) * DEC_;
#pragma unroll
            for (int j = 0; j < 8; j++) {
                const int n = n0 + wn * 64 + j * 8 + qcol;
                float2 o;
                o.x = acc[i][j][half * 2 + 0] + bias[n]     + pe[n]     + ve[n];
                o.y = acc[i][j][half * 2 + 1] + bias[n + 1] + pe[n + 1] + ve[n + 1];
                *(float2*)(op + n) = o;
            }
        }
    }
}

// ---------------------------------------------------------------------------
extern "C" void kernel_launch(void* const* d_in, const int* in_sizes, int n_in,
                              void* d_out, int out_size) {
    const float* x          = (const float*)d_in[0];
    const int*   masked_ids = (const int*)d_in[1];
    const float* Wm         = (const float*)d_in[2];
    const float* bias       = (const float*)d_in[3];
    const float* mask_token = (const float*)d_in[4];
    const float* pos_embed  = (const float*)d_in[5];
    const float* view_embed = (const float*)d_in[6];
    float*       out        = (float*)d_out;

    cudaFuncSetAttribute(gemm_fused_kernel,
                         cudaFuncAttributeMaxDynamicSharedMemorySize, SMEM_TOTAL);

    build_map_kernel<<<B_, 512>>>(masked_ids);
    gemm_fused_kernel<<<NGEMM_ + NFILL_, 256, SMEM_TOTAL>>>(
        x, Wm, bias, pos_embed, view_embed, masked_ids, mask_token, out);
}

// round 8
// speedup vs baseline: 3.4407x; 1.2115x over previous
#include <cuda_runtime.h>
#include <cuda_bf16.h>
#include <cstdint>

#define B_   128
#define T_   196
#define TT_  392      // 2*T
#define ENC_ 1024
#define DEC_ 512
#define V_   98
#define M_   294

// GEMM tiling
#define BM_   128
#define BN_   128
#define BK_   32           // fp32 K elements per chunk
#define NCH_  32           // 1024 / 32
#define STG_BYTES 32768    // per stage: A 16KB + B 16KB (128 rows x 128B each)
#define SMEM_TOTAL (3 * STG_BYTES)   // 98304, 3 stages

#define NGEMM_ 392
#define NFILL_ 96
#define NWORK_ (M_ * B_)

// prep kernel block ranges
#define PREP_X_  3136      // 12544 rows / 4 rows per block
#define PREP_W_  128       // 512 / 4
#define PREP_MAP_ 128
#define PREP_GRID_ (PREP_X_ + PREP_W_ + PREP_MAP_)

// scratch: split operands, layout [(row*32 + ch)*128B] = hi 64B | lo 64B
__device__ __align__(128) unsigned char g_xsplit[(size_t)12544 * 32 * 128];
__device__ __align__(128) unsigned char g_wsplit[(size_t)512 * 32 * 128];
__device__ int g_vis_pos[B_ * V_];

// ---------------------------------------------------------------------------
// helpers
// ---------------------------------------------------------------------------
__device__ __forceinline__ uint32_t smem_u32(const void* p) {
    uint32_t a;
    asm("{ .reg .u64 t; cvta.to.shared.u64 t, %1; cvt.u32.u64 %0, t; }"
        : "=r"(a) : "l"(p));
    return a;
}
__device__ __forceinline__ void ldsm_x4(uint32_t* r, uint32_t addr) {
    asm volatile("ldmatrix.sync.aligned.m8n8.x4.shared.b16 {%0,%1,%2,%3}, [%4];"
                 : "=r"(r[0]), "=r"(r[1]), "=r"(r[2]), "=r"(r[3]) : "r"(addr));
}
__device__ __forceinline__ void mma16816(float* d, const uint32_t* a, const uint32_t* b) {
    asm volatile("mma.sync.aligned.m16n8k16.row.col.f32.bf16.bf16.f32 "
                 "{%0,%1,%2,%3},{%4,%5,%6,%7},{%8,%9},{%0,%1,%2,%3};"
                 : "+f"(d[0]), "+f"(d[1]), "+f"(d[2]), "+f"(d[3])
                 : "r"(a[0]), "r"(a[1]), "r"(a[2]), "r"(a[3]),
                   "r"(b[0]), "r"(b[1]));
}
__device__ __forceinline__ void cp16(uint32_t dst, const void* src) {
    asm volatile("cp.async.cg.shared.global [%0], [%1], 16;"
                 :: "r"(dst), "l"(src) : "memory");
}
#define CP_COMMIT() asm volatile("cp.async.commit_group;" ::: "memory")
#define CP_WAIT1()  asm volatile("cp.async.wait_group 1;" ::: "memory")

__device__ __forceinline__ uint32_t swz128(uint32_t off) {
    return off ^ ((off >> 3) & 0x70u);
}
__device__ __forceinline__ uint32_t pack_bf2(__nv_bfloat16 a, __nv_bfloat16 b) {
    return (uint32_t)__bfloat16_as_ushort(a) | ((uint32_t)__bfloat16_as_ushort(b) << 16);
}
__device__ __forceinline__ void split_f4(float4 f, uint2& hi, uint2& lo) {
    __nv_bfloat16 h0 = __float2bfloat16(f.x);
    __nv_bfloat16 h1 = __float2bfloat16(f.y);
    __nv_bfloat16 h2 = __float2bfloat16(f.z);
    __nv_bfloat16 h3 = __float2bfloat16(f.w);
    __nv_bfloat16 l0 = __float2bfloat16(f.x - __bfloat162float(h0));
    __nv_bfloat16 l1 = __float2bfloat16(f.y - __bfloat162float(h1));
    __nv_bfloat16 l2 = __float2bfloat16(f.z - __bfloat162float(h2));
    __nv_bfloat16 l3 = __float2bfloat16(f.w - __bfloat162float(h3));
    hi.x = pack_bf2(h0, h1); hi.y = pack_bf2(h2, h3);
    lo.x = pack_bf2(l0, l1); lo.y = pack_bf2(l2, l3);
}

// ---------------------------------------------------------------------------
// Prep kernel: bids [0,3136) split x, [3136,3264) split W, [3264,3392) map.
// Split layout: per (row, chunk): 32 hi bf16 (64B) | 32 lo bf16 (64B).
// ---------------------------------------------------------------------------
__global__ void prep_kernel(const float* __restrict__ x,
                            const float* __restrict__ Wm,
                            const int* __restrict__ masked_ids) {
    const int bid = blockIdx.x;
    const int tid = threadIdx.x;   // 512

    if (bid < PREP_X_ + PREP_W_) {
        const float* src;
        unsigned char* dst;
        int row0;
        if (bid < PREP_X_) { src = x;  dst = g_xsplit; row0 = bid * 4; }
        else               { src = Wm; dst = g_wsplit; row0 = (bid - PREP_X_) * 4; }
#pragma unroll
        for (int q = 0; q < 2; q++) {
            int fi  = tid + q * 512;        // float4 index, 1024 = 4 rows
            int row = row0 + (fi >> 8);
            int k4  = fi & 255;
            float4 f = *(const float4*)(src + (size_t)row * ENC_ + k4 * 4);
            uint2 hi, lo;
            split_f4(f, hi, lo);
            int ch  = k4 >> 3;
            int pos = k4 & 7;
            size_t base = ((size_t)row * 32 + ch) * 128;
            *(uint2*)(dst + base + pos * 8)      = hi;
            *(uint2*)(dst + base + 64 + pos * 8) = lo;
        }
        return;
    }

    // build_map branch
    __shared__ int flags[TT_];
    __shared__ int scan[TT_];
    const int b = bid - (PREP_X_ + PREP_W_);
    if (tid < TT_) flags[tid] = 1;
    __syncthreads();
    if (tid < M_) flags[masked_ids[b * M_ + tid]] = 0;
    __syncthreads();
    if (tid < TT_) scan[tid] = flags[tid];
    __syncthreads();
    for (int off = 1; off < TT_; off <<= 1) {
        int v = 0;
        if (tid < TT_ && tid >= off) v = scan[tid - off];
        __syncthreads();
        if (tid < TT_) scan[tid] += v;
        __syncthreads();
    }
    if (tid < TT_ && flags[tid]) g_vis_pos[b * V_ + scan[tid] - 1] = tid;
}

// ---------------------------------------------------------------------------
// Fused kernel: bids [0,392) GEMM (cp.async 3-stage pipeline, mma.sync bf16x3,
// scatter epilogue), bids [392,488) masked fill.
// ---------------------------------------------------------------------------
__global__ __launch_bounds__(256, 2)
void gemm_fused_kernel(const float* __restrict__ bias,
                       const float* __restrict__ pos_embed,
                       const float* __restrict__ view_embed,
                       const int*   __restrict__ masked_ids,
                       const float* __restrict__ mask_token,
                       float* __restrict__ out) {
    const int bid = blockIdx.x;
    const int tid = threadIdx.x;

    // ======================= FILL branch =======================
    if (bid >= NGEMM_) {
        const int f = bid - NGEMM_;
        const int d0 = (tid & 127) * 4;
        const int half = tid >> 7;
        float4 mt0 = *(const float4*)(mask_token + d0);
        for (int w = f * 2 + half; w < NWORK_; w += NFILL_ * 2) {
            const int b = w / M_;
            const int m = w - b * M_;
            const int pos = masked_ids[b * M_ + m];
            float4 pe = *(const float4*)(pos_embed + (size_t)pos * DEC_ + d0);
            float4 ve = *(const float4*)(view_embed + (pos >= T_ ? DEC_ : 0) + d0);
            float4 r;
            r.x = mt0.x + pe.x + ve.x;
            r.y = mt0.y + pe.y + ve.y;
            r.z = mt0.z + pe.z + ve.z;
            r.w = mt0.w + pe.w + ve.w;
            *(float4*)(out + ((size_t)b * TT_ + pos) * DEC_ + d0) = r;
        }
        return;
    }

    // ======================= GEMM branch =======================
    extern __shared__ char smem[];
    const uint32_t sb = smem_u32(smem);
    const int lid = tid & 31;
    const int wid = tid >> 5;
    const int wm  = wid & 3;          // 4 m-warps x 32 rows
    const int wn  = wid >> 2;         // 2 n-warps x 64 cols
    const int m0  = (bid % 98) * BM_;
    const int n0  = (bid / 98) * BN_;

    const unsigned char* asrc = g_xsplit + (size_t)m0 * 4096;  // 32*128 B/row
    const unsigned char* bsrc = g_wsplit + (size_t)n0 * 4096;

    // cp.async per-thread mapping: u = tid + j*256, row = u>>3, seg = u&7
    const int curow = tid >> 3;       // +32 per j
    const int cuseg = tid & 7;

    // ldmatrix lane constants (SW128: phys = row*128 + (c ^ ((row&7)<<4)))
    const int ar   = lid & 15;
    const int akh  = lid >> 4;
    const uint32_t xrA   = (uint32_t)((ar & 7) << 4);
    const uint32_t aoff0 = (uint32_t)((wm * 32 + ar) * 128);
    const int brow = ((lid >> 4) << 3) + (lid & 7);
    const int bkh  = (lid >> 3) & 1;
    const uint32_t xrB   = (uint32_t)((brow & 7) << 4);
    const uint32_t boff0 = 16384u + (uint32_t)((wn * 64 + brow) * 128);

    float acc[2][8][4];
#pragma unroll
    for (int i = 0; i < 2; i++)
#pragma unroll
        for (int j = 0; j < 8; j++)
#pragma unroll
            for (int c = 0; c < 4; c++) acc[i][j][c] = 0.0f;

    // ---- issue helper (A: 4 cp / thread, B: 4 cp / thread) ----
    auto issue = [&](int s, int ch) {
        const uint32_t sa = sb + (uint32_t)s * STG_BYTES;
#pragma unroll
        for (int j = 0; j < 4; j++) {
            int u = tid + j * 256;
            uint32_t d = sa + swz128((uint32_t)u * 16);
            cp16(d, asrc + (size_t)(curow + j * 32) * 4096 + ch * 128 + cuseg * 16);
        }
#pragma unroll
        for (int j = 0; j < 4; j++) {
            int u = tid + j * 256;
            uint32_t d = sa + 16384u + swz128((uint32_t)u * 16);
            cp16(d, bsrc + (size_t)(curow + j * 32) * 4096 + ch * 128 + cuseg * 16);
        }
    };

    // ---- prologue: stages 0,1 <- chunks 0,1 ----
    issue(0, 0); CP_COMMIT();
    issue(1, 1); CP_COMMIT();

    int stage = 0;
    for (int ch = 0; ch < NCH_; ch++) {
        CP_WAIT1();
        __syncthreads();
        // all warps are past reads of stage (ch+2)%3 (== (ch-1)%3) -> safe to refill
        if (ch + 2 < NCH_) {
            int ns = stage + 2; if (ns >= 3) ns -= 3;
            issue(ns, ch + 2);
        }
        CP_COMMIT();

        const uint32_t stg = sb + (uint32_t)stage * STG_BYTES;
#pragma unroll
        for (int ks = 0; ks < 2; ks++) {
            const uint32_t cA = (uint32_t)(ks * 32 + akh * 16);
            const uint32_t cB = (uint32_t)(ks * 32 + bkh * 16);
            uint32_t aH[2][4], aL[2][4];
#pragma unroll
            for (int i = 0; i < 2; i++) {
                uint32_t ad = stg + aoff0 + (uint32_t)(i * 2048) + (cA ^ xrA);
                ldsm_x4(aH[i], ad);
                ldsm_x4(aL[i], ad ^ 64u);
            }
#pragma unroll
            for (int jj = 0; jj < 4; jj++) {
                uint32_t bd = stg + boff0 + (uint32_t)(jj * 2048) + (cB ^ xrB);
                uint32_t bh[4], bl[4];
                ldsm_x4(bh, bd);
                ldsm_x4(bl, bd ^ 64u);
#pragma unroll
                for (int i = 0; i < 2; i++) {
                    mma16816(acc[i][2 * jj],     aH[i], bh);
                    mma16816(acc[i][2 * jj],     aH[i], bl);
                    mma16816(acc[i][2 * jj],     aL[i], bh);
                    mma16816(acc[i][2 * jj + 1], aH[i], bh + 2);
                    mma16816(acc[i][2 * jj + 1], aH[i], bl + 2);
                    mma16816(acc[i][2 * jj + 1], aL[i], bh + 2);
                }
            }
        }
        stage++; if (stage >= 3) stage = 0;
    }

    // ---- epilogue: scatter with bias + pos_embed + view_embed ----
    const int qrow = lid >> 2;
    const int qcol = (lid & 3) * 2;
#pragma unroll
    for (int i = 0; i < 2; i++) {
#pragma unroll
        for (int half = 0; half < 2; half++) {
            const int m   = wm * 32 + i * 16 + qrow + half * 8;
            const int r   = m0 + m;
            const int bb  = r / V_;
            const int pos = g_vis_pos[r];
            const float* pe = pos_embed  + (size_t)pos * DEC_;
            const float* ve = view_embed + (pos >= T_ ? DEC_ : 0);
            float* op = out + ((size_t)bb * TT_ + pos) * DEC_;
#pragma unroll
            for (int j = 0; j < 8; j++) {
                const int n = n0 + wn * 64 + j * 8 + qcol;
                float2 o;
                o.x = acc[i][j][half * 2 + 0] + bias[n]     + pe[n]     + ve[n];
                o.y = acc[i][j][half * 2 + 1] + bias[n + 1] + pe[n + 1] + ve[n + 1];
                *(float2*)(op + n) = o;
            }
        }
    }
}

// ---------------------------------------------------------------------------
extern "C" void kernel_launch(void* const* d_in, const int* in_sizes, int n_in,
                              void* d_out, int out_size) {
    const float* x          = (const float*)d_in[0];
    const int*   masked_ids = (const int*)d_in[1];
    const float* Wm         = (const float*)d_in[2];
    const float* bias       = (const float*)d_in[3];
    const float* mask_token = (const float*)d_in[4];
    const float* pos_embed  = (const float*)d_in[5];
    const float* view_embed = (const float*)d_in[6];
    float*       out        = (float*)d_out;

    cudaFuncSetAttribute(gemm_fused_kernel,
                         cudaFuncAttributeMaxDynamicSharedMemorySize, SMEM_TOTAL);

    prep_kernel<<<PREP_GRID_, 512>>>(x, Wm, masked_ids);
    gemm_fused_kernel<<<NGEMM_ + NFILL_, 256, SMEM_TOTAL>>>(
        bias, pos_embed, view_embed, masked_ids, mask_token, out);
}

// round 10
// speedup vs baseline: 5.1222x; 1.4887x over previous
#include <cuda_runtime.h>
#include <cuda_fp16.h>
#include <cstdint>

#define B_   128
#define T_   196
#define TT_  392      // 2*T
#define ENC_ 1024
#define DEC_ 512
#define V_   98
#define M_   294

// GEMM tiling
#define BM_   128
#define BN_   128
#define BK_   64           // fp16 K elements per chunk (128 bytes)
#define NCH_  16           // 1024 / 64
#define STG_BYTES 32768    // per stage: A 16KB + B 16KB (128 rows x 128B)
#define SMEM_TOTAL (3 * STG_BYTES)   // 98304

#define NGEMM_ 392
#define NFILL_ 96
#define NWORK_ (M_ * B_)

// prep kernel block ranges
#define PREP_X_  3136      // 12544 rows / 4 rows per block
#define PREP_W_  128       // 512 / 4
#define PREP_MAP_ 128
#define PREP_GRID_ (PREP_X_ + PREP_W_ + PREP_MAP_)

// scratch: fp16 operands, layout [(row*16 + ch)*128B] = 64 fp16 for k-chunk ch
__device__ __align__(128) unsigned char g_xhalf[(size_t)12544 * 16 * 128];
__device__ __align__(128) unsigned char g_whalf[(size_t)512 * 16 * 128];
__device__ int g_vis_pos[B_ * V_];

// ---------------------------------------------------------------------------
// helpers
// ---------------------------------------------------------------------------
__device__ __forceinline__ uint32_t smem_u32(const void* p) {
    uint32_t a;
    asm("{ .reg .u64 t; cvta.to.shared.u64 t, %1; cvt.u32.u64 %0, t; }"
        : "=r"(a) : "l"(p));
    return a;
}
__device__ __forceinline__ void ldsm_x4(uint32_t* r, uint32_t addr) {
    asm volatile("ldmatrix.sync.aligned.m8n8.x4.shared.b16 {%0,%1,%2,%3}, [%4];"
                 : "=r"(r[0]), "=r"(r[1]), "=r"(r[2]), "=r"(r[3]) : "r"(addr));
}
__device__ __forceinline__ void mma16816(float* d, const uint32_t* a, const uint32_t* b) {
    asm volatile("mma.sync.aligned.m16n8k16.row.col.f32.f16.f16.f32 "
                 "{%0,%1,%2,%3},{%4,%5,%6,%7},{%8,%9},{%0,%1,%2,%3};"
                 : "+f"(d[0]), "+f"(d[1]), "+f"(d[2]), "+f"(d[3])
                 : "r"(a[0]), "r"(a[1]), "r"(a[2]), "r"(a[3]),
                   "r"(b[0]), "r"(b[1]));
}
__device__ __forceinline__ void cp16(uint32_t dst, const void* src) {
    asm volatile("cp.async.cg.shared.global [%0], [%1], 16;"
                 :: "r"(dst), "l"(src) : "memory");
}
#define CP_COMMIT() asm volatile("cp.async.commit_group;" ::: "memory")
#define CP_WAIT1()  asm volatile("cp.async.wait_group 1;" ::: "memory")

__device__ __forceinline__ uint32_t swz128(uint32_t off) {
    return off ^ ((off >> 3) & 0x70u);
}
// convert float4 -> 4 packed fp16 (8 bytes)
__device__ __forceinline__ uint2 cvt_f4h(float4 f) {
    uint2 r;
    __half2 p0 = __floats2half2_rn(f.x, f.y);
    __half2 p1 = __floats2half2_rn(f.z, f.w);
    r.x = *(uint32_t*)&p0;
    r.y = *(uint32_t*)&p1;
    return r;
}

// ---------------------------------------------------------------------------
// Prep kernel: bids [0,3136) convert x, [3136,3264) convert W, [3264,3392) map.
// ---------------------------------------------------------------------------
__global__ void prep_kernel(const float* __restrict__ x,
                            const float* __restrict__ Wm,
                            const int* __restrict__ masked_ids) {
    const int bid = blockIdx.x;
    const int tid = threadIdx.x;   // 512

    if (bid < PREP_X_ + PREP_W_) {
        const float* src;
        unsigned char* dst;
        int row0;
        if (bid < PREP_X_) { src = x;  dst = g_xhalf; row0 = bid * 4; }
        else               { src = Wm; dst = g_whalf; row0 = (bid - PREP_X_) * 4; }
#pragma unroll
        for (int q = 0; q < 2; q++) {
            int fi  = tid + q * 512;        // float4 index, 1024 = 4 rows
            int row = row0 + (fi >> 8);
            int k4  = fi & 255;
            float4 f = *(const float4*)(src + (size_t)row * ENC_ + k4 * 4);
            int ch  = k4 >> 4;              // 16 float4 per 64-elem chunk
            int pos = k4 & 15;
            *(uint2*)(dst + ((size_t)row * 16 + ch) * 128 + pos * 8) = cvt_f4h(f);
        }
        return;
    }

    // build_map branch
    __shared__ int flags[TT_];
    __shared__ int scan[TT_];
    const int b = bid - (PREP_X_ + PREP_W_);
    if (tid < TT_) flags[tid] = 1;
    __syncthreads();
    if (tid < M_) flags[masked_ids[b * M_ + tid]] = 0;
    __syncthreads();
    if (tid < TT_) scan[tid] = flags[tid];
    __syncthreads();
    for (int off = 1; off < TT_; off <<= 1) {
        int v = 0;
        if (tid < TT_ && tid >= off) v = scan[tid - off];
        __syncthreads();
        if (tid < TT_) scan[tid] += v;
        __syncthreads();
    }
    if (tid < TT_ && flags[tid]) g_vis_pos[b * V_ + scan[tid] - 1] = tid;
}

// ---------------------------------------------------------------------------
// Fused kernel: bids [0,392) GEMM (cp.async 3-stage, mma.sync fp16 single
// product, scatter epilogue), bids [392,488) masked fill.
// ---------------------------------------------------------------------------
__global__ __launch_bounds__(256, 2)
void gemm_fused_kernel(const float* __restrict__ bias,
                       const float* __restrict__ pos_embed,
                       const float* __restrict__ view_embed,
                       const int*   __restrict__ masked_ids,
                       const float* __restrict__ mask_token,
                       float* __restrict__ out) {
    const int bid = blockIdx.x;
    const int tid = threadIdx.x;

    // ======================= FILL branch =======================
    if (bid >= NGEMM_) {
        const int f = bid - NGEMM_;
        const int d0 = (tid & 127) * 4;
        const int half = tid >> 7;
        float4 mt0 = *(const float4*)(mask_token + d0);
        for (int w = f * 2 + half; w < NWORK_; w += NFILL_ * 2) {
            const int b = w / M_;
            const int m = w - b * M_;
            const int pos = masked_ids[b * M_ + m];
            float4 pe = *(const float4*)(pos_embed + (size_t)pos * DEC_ + d0);
            float4 ve = *(const float4*)(view_embed + (pos >= T_ ? DEC_ : 0) + d0);
            float4 r;
            r.x = mt0.x + pe.x + ve.x;
            r.y = mt0.y + pe.y + ve.y;
            r.z = mt0.z + pe.z + ve.z;
            r.w = mt0.w + pe.w + ve.w;
            *(float4*)(out + ((size_t)b * TT_ + pos) * DEC_ + d0) = r;
        }
        return;
    }

    // ======================= GEMM branch =======================
    extern __shared__ char smem[];
    const uint32_t sb = smem_u32(smem);
    const int lid = tid & 31;
    const int wid = tid >> 5;
    const int wm  = wid & 3;          // 4 m-warps x 32 rows
    const int wn  = wid >> 2;         // 2 n-warps x 64 cols
    const int m0  = (bid % 98) * BM_;
    const int n0  = (bid / 98) * BN_;

    const unsigned char* asrc = g_xhalf + (size_t)m0 * 2048;   // 16*128 B/row
    const unsigned char* bsrc = g_whalf + (size_t)n0 * 2048;

    // cp.async per-thread mapping: u = tid + j*256, row = u>>3, seg = u&7
    const int curow = tid >> 3;       // +32 per j
    const int cuseg = tid & 7;

    // ldmatrix lane constants (SW128: phys = row*128 + (c ^ ((row&7)<<4)))
    const int ar   = lid & 15;
    const int akh  = lid >> 4;
    const uint32_t xrA   = (uint32_t)((ar & 7) << 4);
    const uint32_t aoff0 = (uint32_t)((wm * 32 + ar) * 128);
    const int brow = ((lid >> 4) << 3) + (lid & 7);
    const int bkh  = (lid >> 3) & 1;
    const uint32_t xrB   = (uint32_t)((brow & 7) << 4);
    const uint32_t boff0 = 16384u + (uint32_t)((wn * 64 + brow) * 128);

    float acc[2][8][4];
#pragma unroll
    for (int i = 0; i < 2; i++)
#pragma unroll
        for (int j = 0; j < 8; j++)
#pragma unroll
            for (int c = 0; c < 4; c++) acc[i][j][c] = 0.0f;

    // ---- issue helper (A: 4 cp / thread, B: 4 cp / thread) ----
    auto issue = [&](int s, int ch) {
        const uint32_t sa = sb + (uint32_t)s * STG_BYTES;
#pragma unroll
        for (int j = 0; j < 4; j++) {
            int u = tid + j * 256;
            uint32_t d = sa + swz128((uint32_t)u * 16);
            cp16(d, asrc + (size_t)(curow + j * 32) * 2048 + ch * 128 + cuseg * 16);
        }
#pragma unroll
        for (int j = 0; j < 4; j++) {
            int u = tid + j * 256;
            uint32_t d = sa + 16384u + swz128((uint32_t)u * 16);
            cp16(d, bsrc + (size_t)(curow + j * 32) * 2048 + ch * 128 + cuseg * 16);
        }
    };

    // ---- prologue: stages 0,1 <- chunks 0,1 ----
    issue(0, 0); CP_COMMIT();
    issue(1, 1); CP_COMMIT();

    int stage = 0;
    for (int ch = 0; ch < NCH_; ch++) {
        CP_WAIT1();
        __syncthreads();
        if (ch + 2 < NCH_) {
            int ns = stage + 2; if (ns >= 3) ns -= 3;
            issue(ns, ch + 2);
        }
        CP_COMMIT();

        const uint32_t stg = sb + (uint32_t)stage * STG_BYTES;
#pragma unroll
        for (int ks = 0; ks < 4; ks++) {
            const uint32_t cA = (uint32_t)(ks * 32 + akh * 16);
            const uint32_t cB = (uint32_t)(ks * 32 + bkh * 16);
            uint32_t aH[2][4];
#pragma unroll
            for (int i = 0; i < 2; i++) {
                uint32_t ad = stg + aoff0 + (uint32_t)(i * 2048) + (cA ^ xrA);
                ldsm_x4(aH[i], ad);
            }
#pragma unroll
            for (int jj = 0; jj < 4; jj++) {
                uint32_t bd = stg + boff0 + (uint32_t)(jj * 2048) + (cB ^ xrB);
                uint32_t bh[4];
                ldsm_x4(bh, bd);
#pragma unroll
                for (int i = 0; i < 2; i++) {
                    mma16816(acc[i][2 * jj],     aH[i], bh);
                    mma16816(acc[i][2 * jj + 1], aH[i], bh + 2);
                }
            }
        }
        stage++; if (stage >= 3) stage = 0;
    }

    // ---- epilogue: scatter with bias + pos_embed + view_embed ----
    const int qrow = lid >> 2;
    const int qcol = (lid & 3) * 2;
#pragma unroll
    for (int i = 0; i < 2; i++) {
#pragma unroll
        for (int half = 0; half < 2; half++) {
            const int m   = wm * 32 + i * 16 + qrow + half * 8;
            const int r   = m0 + m;
            const int bb  = r / V_;
            const int pos = g_vis_pos[r];
            const float* pe = pos_embed  + (size_t)pos * DEC_;
            const float* ve = view_embed + (pos >= T_ ? DEC_ : 0);
            float* op = out + ((size_t)bb * TT_ + pos) * DEC_;
#pragma unroll
            for (int j = 0; j < 8; j++) {
                const int n = n0 + wn * 64 + j * 8 + qcol;
                float2 o;
                o.x = acc[i][j][half * 2 + 0] + bias[n]     + pe[n]     + ve[n];
                o.y = acc[i][j][half * 2 + 1] + bias[n + 1] + pe[n + 1] + ve[n + 1];
                *(float2*)(op + n) = o;
            }
        }
    }
}

// ---------------------------------------------------------------------------
extern "C" void kernel_launch(void* const* d_in, const int* in_sizes, int n_in,
                              void* d_out, int out_size) {
    const float* x          = (const float*)d_in[0];
    const int*   masked_ids = (const int*)d_in[1];
    const float* Wm         = (const float*)d_in[2];
    const float* bias       = (const float*)d_in[3];
    const float* mask_token = (const float*)d_in[4];
    const float* pos_embed  = (const float*)d_in[5];
    const float* view_embed = (const float*)d_in[6];
    float*       out        = (float*)d_out;

    cudaFuncSetAttribute(gemm_fused_kernel,
                         cudaFuncAttributeMaxDynamicSharedMemorySize, SMEM_TOTAL);

    prep_kernel<<<PREP_GRID_, 512>>>(x, Wm, masked_ids);
    gemm_fused_kernel<<<NGEMM_ + NFILL_, 256, SMEM_TOTAL>>>(
        bias, pos_embed, view_embed, masked_ids, mask_token, out);
}

// round 12
// speedup vs baseline: 5.3313x; 1.0408x over previous
#include <cuda_runtime.h>
#include <cuda_fp16.h>
#include <cstdint>

#define B_   128
#define T_   196
#define TT_  392      // 2*T
#define ENC_ 1024
#define DEC_ 512
#define V_   98
#define M_   294

// GEMM tiling: CTA tile 128x64, warp tile 32x32, 8 warps
#define BK_   64           // fp16 K elements per chunk (128 bytes)
#define NCH_  16           // 1024 / 64
#define STG_BYTES 24576    // per stage: A 16KB (128x128B) + B 8KB (64x128B)
#define B_OFF  16384
#define SMEM_TOTAL (3 * STG_BYTES)   // 73728

#define NGEMM_ 784          // 98 m-tiles x 8 n-tiles
#define NFILL_ 96
#define NWORK_ (M_ * B_)

// prep kernel block ranges
#define PREP_X_  3136      // 12544 rows / 4 rows per block
#define PREP_W_  128       // 512 / 4
#define PREP_MAP_ 128
#define PREP_GRID_ (PREP_X_ + PREP_W_ + PREP_MAP_)

// scratch: fp16 operands, layout [(row*16 + ch)*128B] = 64 fp16 for k-chunk ch
__device__ __align__(128) unsigned char g_xhalf[(size_t)12544 * 16 * 128];
__device__ __align__(128) unsigned char g_whalf[(size_t)512 * 16 * 128];
__device__ int g_vis_pos[B_ * V_];

// ---------------------------------------------------------------------------
// helpers
// ---------------------------------------------------------------------------
__device__ __forceinline__ uint32_t smem_u32(const void* p) {
    uint32_t a;
    asm("{ .reg .u64 t; cvta.to.shared.u64 t, %1; cvt.u32.u64 %0, t; }"
        : "=r"(a) : "l"(p));
    return a;
}
__device__ __forceinline__ void ldsm_x4(uint32_t* r, uint32_t addr) {
    asm volatile("ldmatrix.sync.aligned.m8n8.x4.shared.b16 {%0,%1,%2,%3}, [%4];"
                 : "=r"(r[0]), "=r"(r[1]), "=r"(r[2]), "=r"(r[3]) : "r"(addr));
}
__device__ __forceinline__ void mma16816(float* d, const uint32_t* a, const uint32_t* b) {
    asm volatile("mma.sync.aligned.m16n8k16.row.col.f32.f16.f16.f32 "
                 "{%0,%1,%2,%3},{%4,%5,%6,%7},{%8,%9},{%0,%1,%2,%3};"
                 : "+f"(d[0]), "+f"(d[1]), "+f"(d[2]), "+f"(d[3])
                 : "r"(a[0]), "r"(a[1]), "r"(a[2]), "r"(a[3]),
                   "r"(b[0]), "r"(b[1]));
}
__device__ __forceinline__ void cp16(uint32_t dst, const void* src) {
    asm volatile("cp.async.cg.shared.global [%0], [%1], 16;"
                 :: "r"(dst), "l"(src) : "memory");
}
#define CP_COMMIT() asm volatile("cp.async.commit_group;" ::: "memory")
#define CP_WAIT1()  asm volatile("cp.async.wait_group 1;" ::: "memory")

__device__ __forceinline__ uint32_t swz128(uint32_t off) {
    return off ^ ((off >> 3) & 0x70u);
}
__device__ __forceinline__ uint2 cvt_f4h(float4 f) {
    uint2 r;
    __half2 p0 = __floats2half2_rn(f.x, f.y);
    __half2 p1 = __floats2half2_rn(f.z, f.w);
    r.x = *(uint32_t*)&p0;
    r.y = *(uint32_t*)&p1;
    return r;
}

// ---------------------------------------------------------------------------
// Prep kernel: bids [0,3136) convert x, [3136,3264) convert W, [3264,3392) map.
// ---------------------------------------------------------------------------
__global__ void prep_kernel(const float* __restrict__ x,
                            const float* __restrict__ Wm,
                            const int* __restrict__ masked_ids) {
    const int bid = blockIdx.x;
    const int tid = threadIdx.x;   // 512

    if (bid < PREP_X_ + PREP_W_) {
        const float* src;
        unsigned char* dst;
        int row0;
        if (bid < PREP_X_) { src = x;  dst = g_xhalf; row0 = bid * 4; }
        else               { src = Wm; dst = g_whalf; row0 = (bid - PREP_X_) * 4; }
#pragma unroll
        for (int q = 0; q < 2; q++) {
            int fi  = tid + q * 512;
            int row = row0 + (fi >> 8);
            int k4  = fi & 255;
            float4 f = *(const float4*)(src + (size_t)row * ENC_ + k4 * 4);
            int ch  = k4 >> 4;
            int pos = k4 & 15;
            *(uint2*)(dst + ((size_t)row * 16 + ch) * 128 + pos * 8) = cvt_f4h(f);
        }
        return;
    }

    // build_map branch
    __shared__ int flags[TT_];
    __shared__ int scan[TT_];
    const int b = bid - (PREP_X_ + PREP_W_);
    if (tid < TT_) flags[tid] = 1;
    __syncthreads();
    if (tid < M_) flags[masked_ids[b * M_ + tid]] = 0;
    __syncthreads();
    if (tid < TT_) scan[tid] = flags[tid];
    __syncthreads();
    for (int off = 1; off < TT_; off <<= 1) {
        int v = 0;
        if (tid < TT_ && tid >= off) v = scan[tid - off];
        __syncthreads();
        if (tid < TT_) scan[tid] += v;
        __syncthreads();
    }
    if (tid < TT_ && flags[tid]) g_vis_pos[b * V_ + scan[tid] - 1] = tid;
}

// ---------------------------------------------------------------------------
// Fused kernel: bids [0,784) GEMM 128x64 tiles (cp.async 3-stage, fp16 mma,
// scatter epilogue), bids [784,880) masked fill.
// ---------------------------------------------------------------------------
__global__ __launch_bounds__(256, 3)
void gemm_fused_kernel(const float* __restrict__ bias,
                       const float* __restrict__ pos_embed,
                       const float* __restrict__ view_embed,
                       const int*   __restrict__ masked_ids,
                       const float* __restrict__ mask_token,
                       float* __restrict__ out) {
    const int bid = blockIdx.x;
    const int tid = threadIdx.x;

    // ======================= FILL branch =======================
    if (bid >= NGEMM_) {
        const int f = bid - NGEMM_;
        const int d0 = (tid & 127) * 4;
        const int half = tid >> 7;
        float4 mt0 = *(const float4*)(mask_token + d0);
        for (int w = f * 2 + half; w < NWORK_; w += NFILL_ * 2) {
            const int b = w / M_;
            const int m = w - b * M_;
            const int pos = masked_ids[b * M_ + m];
            float4 pe = *(const float4*)(pos_embed + (size_t)pos * DEC_ + d0);
            float4 ve = *(const float4*)(view_embed + (pos >= T_ ? DEC_ : 0) + d0);
            float4 r;
            r.x = mt0.x + pe.x + ve.x;
            r.y = mt0.y + pe.y + ve.y;
            r.z = mt0.z + pe.z + ve.z;
            r.w = mt0.w + pe.w + ve.w;
            *(float4*)(out + ((size_t)b * TT_ + pos) * DEC_ + d0) = r;
        }
        return;
    }

    // ======================= GEMM branch =======================
    extern __shared__ char smem[];
    const uint32_t sb = smem_u32(smem);
    const int lid = tid & 31;
    const int wid = tid >> 5;
    const int wm  = wid & 3;          // 4 m-warps x 32 rows
    const int wn  = wid >> 2;         // 2 n-warps x 32 cols
    const int m0  = (bid % 98) * 128;
    const int n0  = (bid / 98) * 64;

    const unsigned char* asrc = g_xhalf + (size_t)m0 * 2048;   // 16*128 B/row
    const unsigned char* bsrc = g_whalf + (size_t)n0 * 2048;

    // cp.async per-thread mapping: u = tid + j*256, row = u>>3, seg = u&7
    const int curow = tid >> 3;       // +32 per j
    const int cuseg = tid & 7;

    // ldmatrix lane constants (SW128: phys = row*128 + (c ^ ((row&7)<<4)))
    const int ar   = lid & 15;
    const int akh  = lid >> 4;
    const uint32_t xrA   = (uint32_t)((ar & 7) << 4);
    const uint32_t aoff0 = (uint32_t)((wm * 32 + ar) * 128);
    const int brow = ((lid >> 4) << 3) + (lid & 7);     // 0..15
    const int bkh  = (lid >> 3) & 1;
    const uint32_t xrB   = (uint32_t)((brow & 7) << 4);
    const uint32_t boff0 = B_OFF + (uint32_t)((wn * 32 + brow) * 128);

    float acc[2][4][4];
#pragma unroll
    for (int i = 0; i < 2; i++)
#pragma unroll
        for (int j = 0; j < 4; j++)
#pragma unroll
            for (int c = 0; c < 4; c++) acc[i][j][c] = 0.0f;

    // ---- issue helper (A: 4 cp / thread, B: 2 cp / thread) ----
    auto issue = [&](int s, int ch) {
        const uint32_t sa = sb + (uint32_t)s * STG_BYTES;
#pragma unroll
        for (int j = 0; j < 4; j++) {
            int u = tid + j * 256;
            uint32_t d = sa + swz128((uint32_t)u * 16);
            cp16(d, asrc + (size_t)(curow + j * 32) * 2048 + ch * 128 + cuseg * 16);
        }
#pragma unroll
        for (int j = 0; j < 2; j++) {
            int u = tid + j * 256;
            uint32_t d = sa + B_OFF + swz128((uint32_t)u * 16);
            cp16(d, bsrc + (size_t)(curow + j * 32) * 2048 + ch * 128 + cuseg * 16);
        }
    };

    // ---- prologue: stages 0,1 <- chunks 0,1 ----
    issue(0, 0); CP_COMMIT();
    issue(1, 1); CP_COMMIT();

    int stage = 0;
    for (int ch = 0; ch < NCH_; ch++) {
        CP_WAIT1();
        __syncthreads();
        if (ch + 2 < NCH_) {
            int ns = stage + 2; if (ns >= 3) ns -= 3;
            issue(ns, ch + 2);
        }
        CP_COMMIT();

        const uint32_t stg = sb + (uint32_t)stage * STG_BYTES;
#pragma unroll
        for (int ks = 0; ks < 4; ks++) {
            const uint32_t cA = (uint32_t)(ks * 32 + akh * 16);
            const uint32_t cB = (uint32_t)(ks * 32 + bkh * 16);
            uint32_t aH[2][4];
#pragma unroll
            for (int i = 0; i < 2; i++) {
                uint32_t ad = stg + aoff0 + (uint32_t)(i * 2048) + (cA ^ xrA);
                ldsm_x4(aH[i], ad);
            }
#pragma unroll
            for (int jj = 0; jj < 2; jj++) {
                uint32_t bd = stg + boff0 + (uint32_t)(jj * 2048) + (cB ^ xrB);
                uint32_t bh[4];
                ldsm_x4(bh, bd);
#pragma unroll
                for (int i = 0; i < 2; i++) {
                    mma16816(acc[i][2 * jj],     aH[i], bh);
                    mma16816(acc[i][2 * jj + 1], aH[i], bh + 2);
                }
            }
        }
        stage++; if (stage >= 3) stage = 0;
    }

    // ---- epilogue: scatter with bias + pos_embed + view_embed ----
    const int qrow = lid >> 2;
    const int qcol = (lid & 3) * 2;
#pragma unroll
    for (int i = 0; i < 2; i++) {
#pragma unroll
        for (int half = 0; half < 2; half++) {
            const int m   = wm * 32 + i * 16 + qrow + half * 8;
            const int r   = m0 + m;
            const int bb  = r / V_;
            const int pos = g_vis_pos[r];
            const float* pe = pos_embed  + (size_t)pos * DEC_;
            const float* ve = view_embed + (pos >= T_ ? DEC_ : 0);
            float* op = out + ((size_t)bb * TT_ + pos) * DEC_;
#pragma unroll
            for (int j = 0; j < 4; j++) {
                const int n = n0 + wn * 32 + j * 8 + qcol;
                float2 o;
                o.x = acc[i][j][half * 2 + 0] + bias[n]     + pe[n]     + ve[n];
                o.y = acc[i][j][half * 2 + 1] + bias[n + 1] + pe[n + 1] + ve[n + 1];
                *(float2*)(op + n) = o;
            }
        }
    }
}

// ---------------------------------------------------------------------------
extern "C" void kernel_launch(void* const* d_in, const int* in_sizes, int n_in,
                              void* d_out, int out_size) {
    const float* x          = (const float*)d_in[0];
    const int*   masked_ids = (const int*)d_in[1];
    const float* Wm         = (const float*)d_in[2];
    const float* bias       = (const float*)d_in[3];
    const float* mask_token = (const float*)d_in[4];
    const float* pos_embed  = (const float*)d_in[5];
    const float* view_embed = (const float*)d_in[6];
    float*       out        = (float*)d_out;

    cudaFuncSetAttribute(gemm_fused_kernel,
                         cudaFuncAttributeMaxDynamicSharedMemorySize, SMEM_TOTAL);

    prep_kernel<<<PREP_GRID_, 512>>>(x, Wm, masked_ids);
    gemm_fused_kernel<<<NGEMM_ + NFILL_, 256, SMEM_TOTAL>>>(
        bias, pos_embed, view_embed, masked_ids, mask_token, out);
}